// round 5
// baseline (speedup 1.0000x reference)
#include <cuda_runtime.h>
#include <cuda_bf16.h>
#include <cstdint>

#define BSZ 4096
#define CSZ 1024
#define NT  32          // 4096 / 128 tiles
#define HALF_N 8388608u // (4096*4096)/2
#define NCHUNK 16       // K = 1024 bf16 / 64 per chunk
#define STAGES 3
#define NHARD (NT * (NT + 1) / 2)      // 528
#define NRAND (BSZ / 2)                // 2048
#define TOTB  (NHARD + NRAND)          // 2576

// ---------------- scratch (no allocations allowed) ----------------
__device__ float               g_sq[BSZ];
__device__ float               g_row_ce[BSZ];
__device__ float               g_row_nce[BSZ];
__device__ unsigned long long  g_hard_key[BSZ];
__device__ int                 g_rand_idx[BSZ];
__device__ __nv_bfloat16       g_xb16[BSZ * CSZ];   // bf16 copy of outs, 8 MB

// orderable encoding of float for integer max
__device__ __forceinline__ unsigned int f2o(float f) {
    unsigned int u = __float_as_uint(f);
    return (u & 0x80000000u) ? ~u : (u | 0x80000000u);
}

// ---------------- warp MMA helpers (non-'a' PTX only) ----------------
__device__ __forceinline__ uint32_t smem_u32(const void* p) {
    uint32_t a;
    asm("{ .reg .u64 t; cvta.to.shared.u64 t, %1; cvt.u32.u64 %0, t; }" : "=r"(a) : "l"(p));
    return a;
}
__device__ __forceinline__ void ldm_x4(uint32_t* r, uint32_t addr) {
    asm volatile("ldmatrix.sync.aligned.m8n8.x4.shared.b16 {%0,%1,%2,%3}, [%4];"
                 : "=r"(r[0]), "=r"(r[1]), "=r"(r[2]), "=r"(r[3]) : "r"(addr));
}
__device__ __forceinline__ void mma16816(float* c, const uint32_t* a,
                                         uint32_t b0, uint32_t b1) {
    asm volatile("mma.sync.aligned.m16n8k16.row.col.f32.bf16.bf16.f32 "
                 "{%0,%1,%2,%3}, {%4,%5,%6,%7}, {%8,%9}, {%0,%1,%2,%3};"
                 : "+f"(c[0]), "+f"(c[1]), "+f"(c[2]), "+f"(c[3])
                 : "r"(a[0]), "r"(a[1]), "r"(a[2]), "r"(a[3]), "r"(b0), "r"(b1));
}
#define CP_ASYNC16(dst, src) \
    asm volatile("cp.async.cg.shared.global [%0], [%1], 16;" :: "r"(dst), "l"(src))
#define CP_COMMIT() asm volatile("cp.async.commit_group;")
#define CP_WAIT2()  asm volatile("cp.async.wait_group 2;" ::: "memory")

// JAX Threefry-2x32 (20 rounds), key = (0, 42) for jax.random.key(42)
__device__ __forceinline__ void threefry2x32(unsigned int k0, unsigned int k1,
                                             unsigned int x0, unsigned int x1,
                                             unsigned int& o0, unsigned int& o1) {
    unsigned int ks2 = k0 ^ k1 ^ 0x1BD11BDAu;
#define TF_RND(r) { x0 += x1; x1 = (x1 << (r)) | (x1 >> (32 - (r))); x1 ^= x0; }
    x0 += k0;  x1 += k1;
    TF_RND(13) TF_RND(15) TF_RND(26) TF_RND(6)
    x0 += k1;  x1 += ks2 + 1u;
    TF_RND(17) TF_RND(29) TF_RND(16) TF_RND(24)
    x0 += ks2; x1 += k0 + 2u;
    TF_RND(13) TF_RND(15) TF_RND(26) TF_RND(6)
    x0 += k0;  x1 += k1 + 3u;
    TF_RND(17) TF_RND(29) TF_RND(16) TF_RND(24)
    x0 += k1;  x1 += ks2 + 4u;
    TF_RND(13) TF_RND(15) TF_RND(26) TF_RND(6)
    x0 += ks2; x1 += k0 + 5u;
#undef TF_RND
    o0 = x0; o1 = x1;
}

// ---------------- K_prep: init + bf16 cvt + row stats (fused) --------------
__global__ void k_prep(const float* __restrict__ outs,
                       const int* __restrict__ label) {
    int row = blockIdx.x;
    int t = threadIdx.x;            // 256 threads, 4 floats each
    float4 v = ((const float4*)(outs + (size_t)row * CSZ))[t];

    __nv_bfloat162 p0 = __floats2bfloat162_rn(v.x, v.y);
    __nv_bfloat162 p1 = __floats2bfloat162_rn(v.z, v.w);
    uint2 o; o.x = *(unsigned*)&p0; o.y = *(unsigned*)&p1;
    ((uint2*)g_xb16)[(size_t)row * 256 + t] = o;

    float mx = fmaxf(fmaxf(v.x, v.y), fmaxf(v.z, v.w));
    #pragma unroll
    for (int q = 16; q; q >>= 1) mx = fmaxf(mx, __shfl_xor_sync(0xFFFFFFFFu, mx, q));
    __shared__ float sm[8];
    int w = t >> 5, l = t & 31;
    if (l == 0) sm[w] = mx;
    __syncthreads();
    if (t == 0) {
        float m = sm[0];
        #pragma unroll
        for (int q = 1; q < 8; q++) m = fmaxf(m, sm[q]);
        sm[0] = m;
    }
    __syncthreads();
    mx = sm[0];

    float es = expf(v.x - mx) + expf(v.y - mx) + expf(v.z - mx) + expf(v.w - mx);
    float qs = v.x * v.x + v.y * v.y + v.z * v.z + v.w * v.w;
    #pragma unroll
    for (int q = 16; q; q >>= 1) {
        es += __shfl_xor_sync(0xFFFFFFFFu, es, q);
        qs += __shfl_xor_sync(0xFFFFFFFFu, qs, q);
    }
    __shared__ float se[8], sq2[8];
    if (l == 0) { se[w] = es; sq2[w] = qs; }
    __syncthreads();
    if (t == 0) {
        float E = 0.f, Q = 0.f;
        #pragma unroll
        for (int q = 0; q < 8; q++) { E += se[q]; Q += sq2[q]; }
        int lab = label[row];
        g_row_ce[row] = logf(E) + mx - outs[(size_t)row * CSZ + lab];
        g_sq[row] = Q;
        g_hard_key[row] = 0ull;
    }
}

// ---------------- K_mine: heterogeneous hard-GEMM + rand-threefry ----------
// Block b is a hard-tile block iff floor((b+1)*33/161) > floor(b*33/161):
// exactly 528 hard blocks (idx = floor(b*33/161)) interleaved 1:~4 with
// 2048 rand blocks (idx = b - floor(b*33/161)). Hard blocks: bf16 HMMA
// 128x128 Gram tile + dual-orientation masked argmax. Rand blocks: JAX
// threefry gumbel-argmax (integer shortcut) for 2 anchor rows.
extern __shared__ __align__(1024) unsigned char dsm[];  // 96 KB

__global__ __launch_bounds__(256, 2)
void k_mine(const int* __restrict__ label) {
    int b = blockIdx.x;
    int f0 = (int)(((long long)b * 33) / 161);
    int f1 = (int)(((long long)(b + 1) * 33) / 161);
    int t = threadIdx.x;

    if (f1 > f0) {
        // ================= HARD block =================
        int p = f0;
        int bi = 0, rem = p, width = NT;
        while (rem >= width) { rem -= width; bi++; width--; }
        int bj = bi + rem;
        int i0 = bi * 128, j0 = bj * 128;

        __shared__ int   s_li[128], s_lj[128];
        __shared__ float s_sqi[128], s_sqj[128];

        int lane = t & 31, wid = t >> 5;
        int wm = wid & 1, wn = wid >> 1;
        uint32_t dynb = smem_u32(dsm);

        if (t < 128) {
            s_li[t] = label[i0 + t]; s_sqi[t] = g_sq[i0 + t];
            s_lj[t] = label[j0 + t]; s_sqj[t] = g_sq[j0 + t];
        }

        int lrow = t >> 1;
        int lseg = (t & 1) * 4;
        const char* gA = (const char*)g_xb16 + (size_t)(i0 + lrow) * 2048 + lseg * 16;
        const char* gB = (const char*)g_xb16 + (size_t)(j0 + lrow) * 2048 + lseg * 16;
        uint32_t dA[4], dB[4];
        #pragma unroll
        for (int q = 0; q < 4; q++) {
            unsigned off = (unsigned)lrow * 128u + (unsigned)(lseg + q) * 16u;
            unsigned sw = off ^ ((off >> 3) & 0x70u);
            dA[q] = sw; dB[q] = sw + 16384u;
        }

        #pragma unroll
        for (int s = 0; s < STAGES; s++) {
            uint32_t sb = dynb + s * 32768u;
            #pragma unroll
            for (int q = 0; q < 4; q++) {
                CP_ASYNC16(sb + dA[q], gA + s * 128 + q * 16);
                CP_ASYNC16(sb + dB[q], gB + s * 128 + q * 16);
            }
            CP_COMMIT();
        }

        float acc[4][4][4];
        #pragma unroll
        for (int a = 0; a < 4; a++)
            #pragma unroll
            for (int b2 = 0; b2 < 4; b2++)
                #pragma unroll
                for (int c = 0; c < 4; c++) acc[a][b2][c] = 0.f;

        int rowA0 = wm * 64 + (lane & 15);
        int rowB0 = wn * 32 + (lane & 15);
        int kb_l  = (lane & 16);

        for (int c = 0; c < NCHUNK; c++) {
            CP_WAIT2();
            __syncthreads();
            uint32_t sb = dynb + (uint32_t)(c % STAGES) * 32768u;
            #pragma unroll
            for (int ks = 0; ks < 4; ks++) {
                uint32_t afr[4][4], bfr[2][4];
                #pragma unroll
                for (int mi = 0; mi < 4; mi++) {
                    unsigned off = (unsigned)(rowA0 + mi * 16) * 128u + (unsigned)(ks * 32 + kb_l);
                    unsigned sw = off ^ ((off >> 3) & 0x70u);
                    ldm_x4(afr[mi], sb + sw);
                }
                #pragma unroll
                for (int n2 = 0; n2 < 2; n2++) {
                    unsigned off = (unsigned)(rowB0 + n2 * 16) * 128u + (unsigned)(ks * 32 + kb_l);
                    unsigned sw = off ^ ((off >> 3) & 0x70u);
                    ldm_x4(bfr[n2], sb + 16384u + sw);
                }
                #pragma unroll
                for (int mi = 0; mi < 4; mi++)
                    #pragma unroll
                    for (int nj = 0; nj < 4; nj++) {
                        int n2 = nj >> 1, od = nj & 1;
                        mma16816(acc[mi][nj], afr[mi], bfr[n2][od], bfr[n2][od + 2]);
                    }
            }
            __syncthreads();
            if (c + STAGES < NCHUNK) {
                uint32_t sb2 = dynb + (uint32_t)(c % STAGES) * 32768u;
                #pragma unroll
                for (int q = 0; q < 4; q++) {
                    CP_ASYNC16(sb2 + dA[q], gA + (c + STAGES) * 128 + q * 16);
                    CP_ASYNC16(sb2 + dB[q], gB + (c + STAGES) * 128 + q * 16);
                }
            }
            CP_COMMIT();
        }

        // ---- epilogue: masked argmax, both orientations ----
        unsigned long long* redA = (unsigned long long*)dsm;            // [128][4]
        unsigned long long* redB = (unsigned long long*)(dsm + 4096);   // [128][2]
        int tg = lane >> 2, tp = lane & 3;

        #pragma unroll
        for (int mi = 0; mi < 4; mi++)
            #pragma unroll
            for (int h = 0; h < 2; h++) {
                int row = wm * 64 + mi * 16 + tg + h * 8;
                int li = s_li[row];
                unsigned long long best = 0ull;
                #pragma unroll
                for (int nj = 0; nj < 4; nj++)
                    #pragma unroll
                    for (int c2 = 0; c2 < 2; c2++) {
                        int col = wn * 32 + nj * 8 + tp * 2 + c2;
                        if (s_lj[col] != li) {
                            float v = s_sqj[col] - 2.0f * acc[mi][nj][h * 2 + c2];
                            unsigned long long key =
                                ((unsigned long long)f2o(v) << 32) |
                                (unsigned long long)(0xFFFFFFFFu - (unsigned)(j0 + col));
                            if (key > best) best = key;
                        }
                    }
                #pragma unroll
                for (int o = 1; o <= 2; o <<= 1) {
                    unsigned long long ot = __shfl_xor_sync(0xFFFFFFFFu, best, o);
                    if (ot > best) best = ot;
                }
                if (tp == 0) redA[row * 4 + wn] = best;
            }
        __syncthreads();
        if (t < 128) {
            unsigned long long bst = redA[t * 4];
            #pragma unroll
            for (int q = 1; q < 4; q++) if (redA[t * 4 + q] > bst) bst = redA[t * 4 + q];
            if (bst) atomicMax(&g_hard_key[i0 + t], bst);
        }

        if (bi != bj) {
            #pragma unroll
            for (int nj = 0; nj < 4; nj++)
                #pragma unroll
                for (int c2 = 0; c2 < 2; c2++) {
                    int col = wn * 32 + nj * 8 + tp * 2 + c2;
                    int lj = s_lj[col];
                    unsigned long long best = 0ull;
                    #pragma unroll
                    for (int mi = 0; mi < 4; mi++)
                        #pragma unroll
                        for (int h = 0; h < 2; h++) {
                            int row = wm * 64 + mi * 16 + tg + h * 8;
                            if (s_li[row] != lj) {
                                float v = s_sqi[row] - 2.0f * acc[mi][nj][h * 2 + c2];
                                unsigned long long key =
                                    ((unsigned long long)f2o(v) << 32) |
                                    (unsigned long long)(0xFFFFFFFFu - (unsigned)(i0 + row));
                                if (key > best) best = key;
                            }
                        }
                    #pragma unroll
                    for (int o = 4; o <= 16; o <<= 1) {
                        unsigned long long ot = __shfl_xor_sync(0xFFFFFFFFu, best, o);
                        if (ot > best) best = ot;
                    }
                    if (tg == 0) redB[col * 2 + wm] = best;
                }
            __syncthreads();
            if (t < 128) {
                unsigned long long bst = redB[t * 2];
                if (redB[t * 2 + 1] > bst) bst = redB[t * 2 + 1];
                if (bst) atomicMax(&g_hard_key[j0 + t], bst);
            }
        }
    } else {
        // ================= RAND block =================
        int i = b - f0;                     // 0..2047
        int li0 = __ldg(&label[i]);
        int li1 = __ldg(&label[i + 2048]);

        unsigned best0 = 0u, best1 = 0u;
        int bj0 = BSZ - 1, bj1 = BSZ - 1;
        for (int j = t; j < BSZ; j += 256) {
            unsigned int m0 = (unsigned)(i * BSZ + j);
            unsigned int o0, o1;
            threefry2x32(0u, 42u, m0, m0 + HALF_N, o0, o1);
            unsigned v0 = o0 >> 9, v1 = o1 >> 9;
            int lj = __ldg(&label[j]);
            if (lj != li0 && v0 > best0) { best0 = v0; bj0 = j; }
            if (lj != li1 && v1 > best1) { best1 = v1; bj1 = j; }
        }
        unsigned long long k0 = ((unsigned long long)best0 << 32) |
                                (unsigned long long)(0xFFFFFFFFu - (unsigned)bj0);
        unsigned long long k1 = ((unsigned long long)best1 << 32) |
                                (unsigned long long)(0xFFFFFFFFu - (unsigned)bj1);
        #pragma unroll
        for (int o = 16; o; o >>= 1) {
            unsigned long long t0 = __shfl_xor_sync(0xFFFFFFFFu, k0, o);
            unsigned long long t1 = __shfl_xor_sync(0xFFFFFFFFu, k1, o);
            if (t0 > k0) k0 = t0;
            if (t1 > k1) k1 = t1;
        }
        __shared__ unsigned long long w0[8], w1[8];
        int w = t >> 5;
        if ((t & 31) == 0) { w0[w] = k0; w1[w] = k1; }
        __syncthreads();
        if (t == 0) {
            unsigned long long a = w0[0], c = w1[0];
            #pragma unroll
            for (int q = 1; q < 8; q++) {
                if (w0[q] > a) a = w0[q];
                if (w1[q] > c) c = w1[q];
            }
            g_rand_idx[i]        = (int)(0xFFFFFFFFu - (unsigned)(a & 0xFFFFFFFFu)) & (BSZ - 1);
            g_rand_idx[i + 2048] = (int)(0xFFFFFFFFu - (unsigned)(c & 0xFFFFFFFFu)) & (BSZ - 1);
        }
    }
}

// ---------------- K4: gathered dots + 3-way log-softmax -------------------
__global__ void k_nce(const float* __restrict__ outs,
                      const float* __restrict__ centers,
                      const int* __restrict__ label) {
    int i = blockIdx.x;
    int t = threadIdx.x;                 // 128
    int lab = label[i];
    unsigned long long hk = g_hard_key[i];
    int hidx = (int)(0xFFFFFFFFu - (unsigned)(hk & 0xFFFFFFFFu)) & (BSZ - 1);
    int ridx = g_rand_idx[i] & (BSZ - 1);

    const float4* xi = (const float4*)(outs + (size_t)i * CSZ);
    const float4* pc = (const float4*)(centers + (size_t)lab * CSZ);
    const float4* xr = (const float4*)(outs + (size_t)ridx * CSZ);
    const float4* xh = (const float4*)(outs + (size_t)hidx * CSZ);

    float sp = 0.f, sr = 0.f, sh = 0.f;
    #pragma unroll
    for (int q = t; q < CSZ / 4; q += 128) {
        float4 a = xi[q]; float4 p = pc[q]; float4 r = xr[q]; float4 h = xh[q];
        sp += a.x * p.x + a.y * p.y + a.z * p.z + a.w * p.w;
        sr += a.x * r.x + a.y * r.y + a.z * r.z + a.w * r.w;
        sh += a.x * h.x + a.y * h.y + a.z * h.z + a.w * h.w;
    }
    #pragma unroll
    for (int o = 16; o; o >>= 1) {
        sp += __shfl_xor_sync(0xFFFFFFFFu, sp, o);
        sr += __shfl_xor_sync(0xFFFFFFFFu, sr, o);
        sh += __shfl_xor_sync(0xFFFFFFFFu, sh, o);
    }
    __shared__ float ap[4], ar[4], ah[4];
    int w = t >> 5, l = t & 31;
    if (l == 0) { ap[w] = sp; ar[w] = sr; ah[w] = sh; }
    __syncthreads();
    if (t == 0) {
        float P = ap[0] + ap[1] + ap[2] + ap[3];
        float R = ar[0] + ar[1] + ar[2] + ar[3];
        float H = ah[0] + ah[1] + ah[2] + ah[3];
        float m = fmaxf(P, fmaxf(R, H));
        float lse = logf(expf(P - m) + expf(R - m) + expf(H - m)) + m;
        g_row_nce[i] = lse - P;
    }
}

// ---------------- K5: final deterministic reduce --------------------------
__global__ void k_final(float* __restrict__ out) {
    int t = threadIdx.x;                 // 256
    float a = 0.f, b = 0.f;
    for (int i = t; i < BSZ; i += 256) { a += g_row_ce[i]; b += g_row_nce[i]; }
    __shared__ float s1[256], s2[256];
    s1[t] = a; s2[t] = b;
    __syncthreads();
    for (int s = 128; s; s >>= 1) {
        if (t < s) { s1[t] += s1[t + s]; s2[t] += s2[t + s]; }
        __syncthreads();
    }
    if (t == 0)
        out[0] = s1[0] / (float)BSZ + 0.1f * (s2[0] / (float)BSZ);
}

// ---------------- launch ---------------------------------------------------
extern "C" void kernel_launch(void* const* d_in, const int* in_sizes, int n_in,
                              void* d_out, int out_size) {
    const float* outs    = (const float*)d_in[0];
    const float* centers = (const float*)d_in[1];
    const int*   label   = (const int*)d_in[2];

    static bool attr_done = false;
    if (!attr_done) {
        cudaFuncSetAttribute(k_mine, cudaFuncAttributeMaxDynamicSharedMemorySize, 98304);
        attr_done = true;
    }

    k_prep<<<BSZ, 256>>>(outs, label);
    k_mine<<<TOTB, 256, 98304>>>(label);
    k_nce<<<BSZ, 128>>>(outs, centers, label);
    k_final<<<1, 256>>>((float*)d_out);
}

// round 6
// speedup vs baseline: 1.1041x; 1.1041x over previous
#include <cuda_runtime.h>
#include <cuda_bf16.h>
#include <cstdint>

#define BSZ 4096
#define CSZ 1024
#define NT  32          // 4096 / 128 tiles
#define HALF_N 8388608u // (4096*4096)/2
#define NCHUNK 16       // K = 1024 bf16 / 64 per chunk
#define STAGES 3
#define FXSCALE 268435456.0   // 2^28
#define NARRIVE (BSZ * 2)     // k_prep blocks + k_nce blocks

// ---------------- scratch (no allocations allowed) ----------------
__device__ float               g_sq[BSZ];
__device__ unsigned long long  g_hard_key[BSZ];
__device__ int                 g_rand_idx[BSZ];
__device__ __nv_bfloat16       g_xb16[BSZ * CSZ];   // bf16 copy of outs, 8 MB
__device__ unsigned long long  g_acc[2] = {0ull, 0ull};  // fixed-point CE, NCE sums
__device__ unsigned int        g_done = 0u;

// orderable encoding of float for integer max
__device__ __forceinline__ unsigned int f2o(float f) {
    unsigned int u = __float_as_uint(f);
    return (u & 0x80000000u) ? ~u : (u | 0x80000000u);
}

// ---------------- warp MMA helpers (non-'a' PTX only) ----------------
__device__ __forceinline__ uint32_t smem_u32(const void* p) {
    uint32_t a;
    asm("{ .reg .u64 t; cvta.to.shared.u64 t, %1; cvt.u32.u64 %0, t; }" : "=r"(a) : "l"(p));
    return a;
}
__device__ __forceinline__ void ldm_x4(uint32_t* r, uint32_t addr) {
    asm volatile("ldmatrix.sync.aligned.m8n8.x4.shared.b16 {%0,%1,%2,%3}, [%4];"
                 : "=r"(r[0]), "=r"(r[1]), "=r"(r[2]), "=r"(r[3]) : "r"(addr));
}
__device__ __forceinline__ void mma16816(float* c, const uint32_t* a,
                                         uint32_t b0, uint32_t b1) {
    asm volatile("mma.sync.aligned.m16n8k16.row.col.f32.bf16.bf16.f32 "
                 "{%0,%1,%2,%3}, {%4,%5,%6,%7}, {%8,%9}, {%0,%1,%2,%3};"
                 : "+f"(c[0]), "+f"(c[1]), "+f"(c[2]), "+f"(c[3])
                 : "r"(a[0]), "r"(a[1]), "r"(a[2]), "r"(a[3]), "r"(b0), "r"(b1));
}
#define CP_ASYNC16(dst, src) \
    asm volatile("cp.async.cg.shared.global [%0], [%1], 16;" :: "r"(dst), "l"(src))
#define CP_COMMIT() asm volatile("cp.async.commit_group;")
#define CP_WAIT2()  asm volatile("cp.async.wait_group 2;" ::: "memory")

// JAX Threefry-2x32 (20 rounds), key = (0, 42) for jax.random.key(42)
__device__ __forceinline__ void threefry2x32(unsigned int k0, unsigned int k1,
                                             unsigned int x0, unsigned int x1,
                                             unsigned int& o0, unsigned int& o1) {
    unsigned int ks2 = k0 ^ k1 ^ 0x1BD11BDAu;
#define TF_RND(r) { x0 += x1; x1 = (x1 << (r)) | (x1 >> (32 - (r))); x1 ^= x0; }
    x0 += k0;  x1 += k1;
    TF_RND(13) TF_RND(15) TF_RND(26) TF_RND(6)
    x0 += k1;  x1 += ks2 + 1u;
    TF_RND(17) TF_RND(29) TF_RND(16) TF_RND(24)
    x0 += ks2; x1 += k0 + 2u;
    TF_RND(13) TF_RND(15) TF_RND(26) TF_RND(6)
    x0 += k0;  x1 += k1 + 3u;
    TF_RND(17) TF_RND(29) TF_RND(16) TF_RND(24)
    x0 += k1;  x1 += ks2 + 4u;
    TF_RND(13) TF_RND(15) TF_RND(26) TF_RND(6)
    x0 += ks2; x1 += k0 + 5u;
#undef TF_RND
    o0 = x0; o1 = x1;
}

// ---------------- K_prep: init + bf16 cvt + row stats + CE accumulate ------
__global__ void k_prep(const float* __restrict__ outs,
                       const int* __restrict__ label) {
    int row = blockIdx.x;
    int t = threadIdx.x;            // 256 threads, 4 floats each
    float4 v = ((const float4*)(outs + (size_t)row * CSZ))[t];

    __nv_bfloat162 p0 = __floats2bfloat162_rn(v.x, v.y);
    __nv_bfloat162 p1 = __floats2bfloat162_rn(v.z, v.w);
    uint2 o; o.x = *(unsigned*)&p0; o.y = *(unsigned*)&p1;
    ((uint2*)g_xb16)[(size_t)row * 256 + t] = o;

    float mx = fmaxf(fmaxf(v.x, v.y), fmaxf(v.z, v.w));
    #pragma unroll
    for (int q = 16; q; q >>= 1) mx = fmaxf(mx, __shfl_xor_sync(0xFFFFFFFFu, mx, q));
    __shared__ float sm[8];
    int w = t >> 5, l = t & 31;
    if (l == 0) sm[w] = mx;
    __syncthreads();
    if (t == 0) {
        float m = sm[0];
        #pragma unroll
        for (int q = 1; q < 8; q++) m = fmaxf(m, sm[q]);
        sm[0] = m;
    }
    __syncthreads();
    mx = sm[0];

    float es = expf(v.x - mx) + expf(v.y - mx) + expf(v.z - mx) + expf(v.w - mx);
    float qs = v.x * v.x + v.y * v.y + v.z * v.z + v.w * v.w;
    #pragma unroll
    for (int q = 16; q; q >>= 1) {
        es += __shfl_xor_sync(0xFFFFFFFFu, es, q);
        qs += __shfl_xor_sync(0xFFFFFFFFu, qs, q);
    }
    __shared__ float se[8], sq2[8];
    if (l == 0) { se[w] = es; sq2[w] = qs; }
    __syncthreads();
    if (t == 0) {
        float E = 0.f, Q = 0.f;
        #pragma unroll
        for (int q = 0; q < 8; q++) { E += se[q]; Q += sq2[q]; }
        int lab = label[row];
        float ce = logf(E) + mx - outs[(size_t)row * CSZ + lab];
        g_sq[row] = Q;
        g_hard_key[row] = 0ull;
        atomicAdd(&g_acc[0], (unsigned long long)__double2ll_rn((double)ce * FXSCALE));
        __threadfence();
        atomicAdd(&g_done, 1u);
    }
}

// ---------------- K2: symmetric Gram via bf16 HMMA + hard-negative argmax --
extern __shared__ __align__(1024) unsigned char dsm[];  // 96 KB

__global__ __launch_bounds__(256, 2)
void k_hard_hmma(const int* __restrict__ label) {
    int p = blockIdx.x;
    int bi = 0, rem = p, width = NT;
    while (rem >= width) { rem -= width; bi++; width--; }
    int bj = bi + rem;
    int i0 = bi * 128, j0 = bj * 128;

    __shared__ int   s_li[128], s_lj[128];
    __shared__ float s_sqi[128], s_sqj[128];

    int t = threadIdx.x;
    int lane = t & 31, wid = t >> 5;
    int wm = wid & 1, wn = wid >> 1;
    uint32_t dynb = smem_u32(dsm);

    if (t < 128) {
        s_li[t] = label[i0 + t]; s_sqi[t] = g_sq[i0 + t];
        s_lj[t] = label[j0 + t]; s_sqj[t] = g_sq[j0 + t];
    }

    int lrow = t >> 1;
    int lseg = (t & 1) * 4;
    const char* gA = (const char*)g_xb16 + (size_t)(i0 + lrow) * 2048 + lseg * 16;
    const char* gB = (const char*)g_xb16 + (size_t)(j0 + lrow) * 2048 + lseg * 16;
    uint32_t dA[4], dB[4];
    #pragma unroll
    for (int q = 0; q < 4; q++) {
        unsigned off = (unsigned)lrow * 128u + (unsigned)(lseg + q) * 16u;
        unsigned sw = off ^ ((off >> 3) & 0x70u);
        dA[q] = sw; dB[q] = sw + 16384u;
    }

    #pragma unroll
    for (int s = 0; s < STAGES; s++) {
        uint32_t sb = dynb + s * 32768u;
        #pragma unroll
        for (int q = 0; q < 4; q++) {
            CP_ASYNC16(sb + dA[q], gA + s * 128 + q * 16);
            CP_ASYNC16(sb + dB[q], gB + s * 128 + q * 16);
        }
        CP_COMMIT();
    }

    float acc[4][4][4];
    #pragma unroll
    for (int a = 0; a < 4; a++)
        #pragma unroll
        for (int b = 0; b < 4; b++)
            #pragma unroll
            for (int c = 0; c < 4; c++) acc[a][b][c] = 0.f;

    int rowA0 = wm * 64 + (lane & 15);
    int rowB0 = wn * 32 + (lane & 15);
    int kb_l  = (lane & 16);

    for (int c = 0; c < NCHUNK; c++) {
        CP_WAIT2();
        __syncthreads();
        uint32_t sb = dynb + (uint32_t)(c % STAGES) * 32768u;
        #pragma unroll
        for (int ks = 0; ks < 4; ks++) {
            uint32_t afr[4][4], bfr[2][4];
            #pragma unroll
            for (int mi = 0; mi < 4; mi++) {
                unsigned off = (unsigned)(rowA0 + mi * 16) * 128u + (unsigned)(ks * 32 + kb_l);
                unsigned sw = off ^ ((off >> 3) & 0x70u);
                ldm_x4(afr[mi], sb + sw);
            }
            #pragma unroll
            for (int n2 = 0; n2 < 2; n2++) {
                unsigned off = (unsigned)(rowB0 + n2 * 16) * 128u + (unsigned)(ks * 32 + kb_l);
                unsigned sw = off ^ ((off >> 3) & 0x70u);
                ldm_x4(bfr[n2], sb + 16384u + sw);
            }
            #pragma unroll
            for (int mi = 0; mi < 4; mi++)
                #pragma unroll
                for (int nj = 0; nj < 4; nj++) {
                    int n2 = nj >> 1, od = nj & 1;
                    mma16816(acc[mi][nj], afr[mi], bfr[n2][od], bfr[n2][od + 2]);
                }
        }
        __syncthreads();
        if (c + STAGES < NCHUNK) {
            uint32_t sb2 = dynb + (uint32_t)(c % STAGES) * 32768u;
            #pragma unroll
            for (int q = 0; q < 4; q++) {
                CP_ASYNC16(sb2 + dA[q], gA + (c + STAGES) * 128 + q * 16);
                CP_ASYNC16(sb2 + dB[q], gB + (c + STAGES) * 128 + q * 16);
            }
        }
        CP_COMMIT();
    }

    // ---- epilogue: masked argmax, both orientations ----
    unsigned long long* redA = (unsigned long long*)dsm;            // [128][4]
    unsigned long long* redB = (unsigned long long*)(dsm + 4096);   // [128][2]
    int tg = lane >> 2, tp = lane & 3;

    #pragma unroll
    for (int mi = 0; mi < 4; mi++)
        #pragma unroll
        for (int h = 0; h < 2; h++) {
            int row = wm * 64 + mi * 16 + tg + h * 8;
            int li = s_li[row];
            unsigned long long best = 0ull;
            #pragma unroll
            for (int nj = 0; nj < 4; nj++)
                #pragma unroll
                for (int c2 = 0; c2 < 2; c2++) {
                    int col = wn * 32 + nj * 8 + tp * 2 + c2;
                    if (s_lj[col] != li) {
                        float v = s_sqj[col] - 2.0f * acc[mi][nj][h * 2 + c2];
                        unsigned long long key =
                            ((unsigned long long)f2o(v) << 32) |
                            (unsigned long long)(0xFFFFFFFFu - (unsigned)(j0 + col));
                        if (key > best) best = key;
                    }
                }
            #pragma unroll
            for (int o = 1; o <= 2; o <<= 1) {
                unsigned long long ot = __shfl_xor_sync(0xFFFFFFFFu, best, o);
                if (ot > best) best = ot;
            }
            if (tp == 0) redA[row * 4 + wn] = best;
        }
    __syncthreads();
    if (t < 128) {
        unsigned long long b = redA[t * 4];
        #pragma unroll
        for (int q = 1; q < 4; q++) if (redA[t * 4 + q] > b) b = redA[t * 4 + q];
        if (b) atomicMax(&g_hard_key[i0 + t], b);
    }

    if (bi != bj) {
        #pragma unroll
        for (int nj = 0; nj < 4; nj++)
            #pragma unroll
            for (int c2 = 0; c2 < 2; c2++) {
                int col = wn * 32 + nj * 8 + tp * 2 + c2;
                int lj = s_lj[col];
                unsigned long long best = 0ull;
                #pragma unroll
                for (int mi = 0; mi < 4; mi++)
                    #pragma unroll
                    for (int h = 0; h < 2; h++) {
                        int row = wm * 64 + mi * 16 + tg + h * 8;
                        if (s_li[row] != lj) {
                            float v = s_sqi[row] - 2.0f * acc[mi][nj][h * 2 + c2];
                            unsigned long long key =
                                ((unsigned long long)f2o(v) << 32) |
                                (unsigned long long)(0xFFFFFFFFu - (unsigned)(i0 + row));
                            if (key > best) best = key;
                        }
                    }
                #pragma unroll
                for (int o = 4; o <= 16; o <<= 1) {
                    unsigned long long ot = __shfl_xor_sync(0xFFFFFFFFu, best, o);
                    if (ot > best) best = ot;
                }
                if (tg == 0) redB[col * 2 + wm] = best;
            }
        __syncthreads();
        if (t < 128) {
            unsigned long long b = redB[t * 2];
            if (redB[t * 2 + 1] > b) b = redB[t * 2 + 1];
            if (b) atomicMax(&g_hard_key[j0 + t], b);
        }
    }
}

// ---------------- K3: JAX gumbel argmax (integer, monotone shortcut) -------
__global__ void k_rand(const int* __restrict__ label) {
    int i = blockIdx.x;                 // 0..2047
    int t = threadIdx.x;                // 256
    __shared__ int slab[BSZ];           // 16 KB
    for (int j = t; j < BSZ; j += 256) slab[j] = label[j];
    __syncthreads();
    int li0 = slab[i], li1 = slab[i + 2048];

    unsigned best0 = 0u, best1 = 0u;
    int bj0 = BSZ - 1, bj1 = BSZ - 1;
    for (int j = t; j < BSZ; j += 256) {
        unsigned int m0 = (unsigned)(i * BSZ + j);
        unsigned int o0, o1;
        threefry2x32(0u, 42u, m0, m0 + HALF_N, o0, o1);
        unsigned v0 = o0 >> 9, v1 = o1 >> 9;
        int lj = slab[j];
        if (lj != li0 && v0 > best0) { best0 = v0; bj0 = j; }
        if (lj != li1 && v1 > best1) { best1 = v1; bj1 = j; }
    }
    unsigned long long k0 = ((unsigned long long)best0 << 32) |
                            (unsigned long long)(0xFFFFFFFFu - (unsigned)bj0);
    unsigned long long k1 = ((unsigned long long)best1 << 32) |
                            (unsigned long long)(0xFFFFFFFFu - (unsigned)bj1);
    #pragma unroll
    for (int o = 16; o; o >>= 1) {
        unsigned long long t0 = __shfl_xor_sync(0xFFFFFFFFu, k0, o);
        unsigned long long t1 = __shfl_xor_sync(0xFFFFFFFFu, k1, o);
        if (t0 > k0) k0 = t0;
        if (t1 > k1) k1 = t1;
    }
    __shared__ unsigned long long w0[8], w1[8];
    int w = t >> 5;
    if ((t & 31) == 0) { w0[w] = k0; w1[w] = k1; }
    __syncthreads();
    if (t == 0) {
        unsigned long long a = w0[0], c = w1[0];
        #pragma unroll
        for (int q = 1; q < 8; q++) {
            if (w0[q] > a) a = w0[q];
            if (w1[q] > c) c = w1[q];
        }
        g_rand_idx[i]        = (int)(0xFFFFFFFFu - (unsigned)(a & 0xFFFFFFFFu)) & (BSZ - 1);
        g_rand_idx[i + 2048] = (int)(0xFFFFFFFFu - (unsigned)(c & 0xFFFFFFFFu)) & (BSZ - 1);
    }
}

// ---------------- K4: gathered dots + 3-way log-softmax + final reduce -----
__global__ void k_nce(const float* __restrict__ outs,
                      const float* __restrict__ centers,
                      const int* __restrict__ label,
                      float* __restrict__ out) {
    int i = blockIdx.x;
    int t = threadIdx.x;                 // 128
    int lab = label[i];
    unsigned long long hk = g_hard_key[i];
    int hidx = (int)(0xFFFFFFFFu - (unsigned)(hk & 0xFFFFFFFFu)) & (BSZ - 1);
    int ridx = g_rand_idx[i] & (BSZ - 1);

    const float4* xi = (const float4*)(outs + (size_t)i * CSZ);
    const float4* pc = (const float4*)(centers + (size_t)lab * CSZ);
    const float4* xr = (const float4*)(outs + (size_t)ridx * CSZ);
    const float4* xh = (const float4*)(outs + (size_t)hidx * CSZ);

    float sp = 0.f, sr = 0.f, sh = 0.f;
    #pragma unroll
    for (int q = t; q < CSZ / 4; q += 128) {
        float4 a = xi[q]; float4 p = pc[q]; float4 r = xr[q]; float4 h = xh[q];
        sp += a.x * p.x + a.y * p.y + a.z * p.z + a.w * p.w;
        sr += a.x * r.x + a.y * r.y + a.z * r.z + a.w * r.w;
        sh += a.x * h.x + a.y * h.y + a.z * h.z + a.w * h.w;
    }
    #pragma unroll
    for (int o = 16; o; o >>= 1) {
        sp += __shfl_xor_sync(0xFFFFFFFFu, sp, o);
        sr += __shfl_xor_sync(0xFFFFFFFFu, sr, o);
        sh += __shfl_xor_sync(0xFFFFFFFFu, sh, o);
    }
    __shared__ float ap[4], ar[4], ah[4];
    int w = t >> 5, l = t & 31;
    if (l == 0) { ap[w] = sp; ar[w] = sr; ah[w] = sh; }
    __syncthreads();
    if (t == 0) {
        float P = ap[0] + ap[1] + ap[2] + ap[3];
        float R = ar[0] + ar[1] + ar[2] + ar[3];
        float H = ah[0] + ah[1] + ah[2] + ah[3];
        float m = fmaxf(P, fmaxf(R, H));
        float lse = logf(expf(P - m) + expf(R - m) + expf(H - m)) + m;
        float nce = lse - P;
        atomicAdd(&g_acc[1], (unsigned long long)__double2ll_rn((double)nce * FXSCALE));
        __threadfence();
        unsigned old = atomicAdd(&g_done, 1u);
        if (old == NARRIVE - 1) {
            // all CE (k_prep) and NCE (k_nce) contributions are in
            double ce_sum  = (double)(long long)g_acc[0] / FXSCALE;
            double nce_sum = (double)(long long)g_acc[1] / FXSCALE;
            out[0] = (float)(ce_sum / (double)BSZ + 0.1 * (nce_sum / (double)BSZ));
            // self-reset for next graph replay
            g_acc[0] = 0ull; g_acc[1] = 0ull;
            __threadfence();
            g_done = 0u;
        }
    }
}

// ---------------- launch ---------------------------------------------------
extern "C" void kernel_launch(void* const* d_in, const int* in_sizes, int n_in,
                              void* d_out, int out_size) {
    const float* outs    = (const float*)d_in[0];
    const float* centers = (const float*)d_in[1];
    const int*   label   = (const int*)d_in[2];

    static cudaStream_t s2 = nullptr;
    static cudaEvent_t ev_fork = nullptr, ev_join = nullptr;
    static bool attr_done = false;
    if (!s2) {
        cudaStreamCreateWithFlags(&s2, cudaStreamNonBlocking);
        cudaEventCreateWithFlags(&ev_fork, cudaEventDisableTiming);
        cudaEventCreateWithFlags(&ev_join, cudaEventDisableTiming);
    }
    if (!attr_done) {
        cudaFuncSetAttribute(k_hard_hmma, cudaFuncAttributeMaxDynamicSharedMemorySize, 98304);
        attr_done = true;
    }

    // fork: k_rand (label-only dependency) runs concurrently with prep+hard
    cudaEventRecord(ev_fork, 0);
    cudaStreamWaitEvent(s2, ev_fork, 0);
    k_rand<<<BSZ / 2, 256, 0, s2>>>(label);
    cudaEventRecord(ev_join, s2);

    k_prep<<<BSZ, 256>>>(outs, label);
    k_hard_hmma<<<NT * (NT + 1) / 2, 256, 98304>>>(label);

    // join
    cudaStreamWaitEvent(0, ev_join, 0);
    k_nce<<<BSZ, 128, 0, 0>>>(outs, centers, label, (float*)d_out);
}